// round 3
// baseline (speedup 1.0000x reference)
#include <cuda_runtime.h>

// Problem constants (shapes fixed by the dataset)
#define T_IN     60          // input-driven timesteps
#define CH       128         // input channels
#define NPIX     4096        // batch rows (pixel samples)
#define HID      128         // hidden size
#define G4       512         // 4*HID gate width
#define RBLK     32          // rows per CTA
#define NCTA     (NPIX / RBLK)  // 128 CTAs
#define NTHREADS 256
#define KT       32          // K tile

// Scratch weights (prepared once per launch). ~770 KB device globals (allowed).
__device__ float g_WtCat[256 * G4];  // [k][g]: k<128 -> W_hh[g][k], k>=128 -> W_ih[g][k-128]
__device__ float g_WsumT[128 * G4];  // [k][g]: W_ih[g][k] + W_hh[g][k]  (AR phase)
__device__ float g_bias[G4];         // b_ih + b_hh

__global__ void prep_kernel(const float* __restrict__ W_ih, const float* __restrict__ W_hh,
                            const float* __restrict__ b_ih, const float* __restrict__ b_hh) {
    int idx = blockIdx.x * blockDim.x + threadIdx.x;
    if (idx < 128 * G4) {
        int k = idx >> 9;       // / 512
        int g = idx & 511;
        float wih = W_ih[g * CH + k];
        float whh = W_hh[g * HID + k];
        g_WtCat[k * G4 + g]         = whh;
        g_WtCat[(128 + k) * G4 + g] = wih;
        g_WsumT[k * G4 + g]         = wih + whh;
    }
    if (idx < G4) g_bias[idx] = b_ih[idx] + b_hh[idx];
}

__device__ __forceinline__ float sigm(float x) {
    return __fdividef(1.0f, 1.0f + __expf(-x));
}
__device__ __forceinline__ float tanh_f(float x) {
    // 2*sigmoid(2x)-1 : cancellation-safe for our gate range, MUFU.EX2-based
    return 2.0f * __fdividef(1.0f, 1.0f + __expf(-2.0f * x)) - 1.0f;
}

// Dynamic smem layout (floats):
//   [0,     4096)  sh_h  [32][128]
//   [4096,  8192)  sh_c  [32][128]
//   [8192, 12320)  sh_x  [32][129]  (padded: conflict-free STS of x tile)
//   [12320,28704)  sh_bg [32][512]  (B K-tile, reused as gates buffer)
#define SMEM_FLOATS 28704
#define SMEM_BYTES  (SMEM_FLOATS * 4)

extern __shared__ float smem[];

__global__ __launch_bounds__(NTHREADS, 1)
void lstm_persist_kernel(const float* __restrict__ image, float* __restrict__ out, int total_t) {
    float* sh_h  = smem;
    float* sh_c  = smem + 4096;
    float* sh_x  = smem + 8192;
    float* sh_bg = smem + 12320;

    const int tid = threadIdx.x;
    const int ty  = tid >> 5;   // 0..7  -> row group (4 rows)
    const int tx  = tid & 31;   // 0..31 -> col lane (cols tx + 32*jj)
    const int row_base = blockIdx.x * RBLK;

    // h = c = 0
    for (int i = tid; i < RBLK * HID; i += NTHREADS) { sh_h[i] = 0.0f; sh_c[i] = 0.0f; }

    for (int t = 0; t < total_t; ++t) {
        const bool ph1 = (t < T_IN);
        const float* __restrict__ Bmat = ph1 ? g_WtCat : g_WsumT;
        const int Ktot = ph1 ? 256 : 128;

        if (ph1) {
            // stage x_t tile: sh_x[r][c] = image[t][c][row_base + r]   (coalesced over r)
            for (int i = tid; i < RBLK * CH; i += NTHREADS) {
                int cc = i >> 5;
                int rr = i & 31;
                sh_x[rr * (CH + 1) + cc] =
                    image[((size_t)t * CH + cc) * (size_t)NPIX + row_base + rr];
            }
        }

        // accumulators init with fused bias
        float acc[4][16];
        #pragma unroll
        for (int jj = 0; jj < 16; ++jj) {
            float bv = g_bias[tx + 32 * jj];
            #pragma unroll
            for (int i = 0; i < 4; ++i) acc[i][jj] = bv;
        }

        for (int kt = 0; kt < Ktot; kt += KT) {
            __syncthreads();  // prev tile (or prev-step gates / h) fully consumed
            // stage B K-tile [KT][512] (L2-resident weights)
            {
                const float4* src = (const float4*)(Bmat + (size_t)kt * G4);
                float4* dst = (float4*)sh_bg;
                for (int i = tid; i < KT * G4 / 4; i += NTHREADS) dst[i] = src[i];
            }
            __syncthreads();

            const float* Abase;
            int Astride;
            if (kt < 128) { Abase = sh_h + (ty * 4) * HID + kt;          Astride = HID; }
            else          { Abase = sh_x + (ty * 4) * (CH + 1) + (kt - 128); Astride = CH + 1; }

            #pragma unroll
            for (int kk = 0; kk < KT; ++kk) {
                float a0 = Abase[0 * Astride + kk];   // warp-broadcast LDS
                float a1 = Abase[1 * Astride + kk];
                float a2 = Abase[2 * Astride + kk];
                float a3 = Abase[3 * Astride + kk];
                const float* brow = sh_bg + kk * G4 + tx;  // bank tx: conflict-free
                #pragma unroll
                for (int jj = 0; jj < 16; ++jj) {
                    float bv = brow[32 * jj];
                    acc[0][jj] += a0 * bv;
                    acc[1][jj] += a1 * bv;
                    acc[2][jj] += a2 * bv;
                    acc[3][jj] += a3 * bv;
                }
            }
        }

        __syncthreads();  // all B reads done -> reuse sh_bg for gates
        #pragma unroll
        for (int i = 0; i < 4; ++i) {
            int r = ty * 4 + i;
            #pragma unroll
            for (int jj = 0; jj < 16; ++jj)
                sh_bg[r * G4 + tx + 32 * jj] = acc[i][jj];
        }
        __syncthreads();

        // epilogue: activations + state update + output write
        #pragma unroll
        for (int i = 0; i < 4; ++i) {
            int r = ty * 4 + i;
            #pragma unroll
            for (int jj = 0; jj < 4; ++jj) {
                int j = tx + 32 * jj;
                float gi = sigm  (sh_bg[r * G4 +           j]);
                float gf = sigm  (sh_bg[r * G4 +     HID + j]);
                float gg = tanh_f(sh_bg[r * G4 + 2 * HID + j]);
                float go = sigm  (sh_bg[r * G4 + 3 * HID + j]);
                float cn = gf * sh_c[r * HID + j] + gi * gg;
                sh_c[r * HID + j] = cn;
                float hn = go * tanh_f(cn);
                sh_h[r * HID + j] = hn;
                out[((size_t)(row_base + r) * total_t + t) * HID + j] = hn;
            }
        }
        // next iteration's first __syncthreads orders sh_h/sh_bg reuse
    }
}

extern "C" void kernel_launch(void* const* d_in, const int* in_sizes, int n_in,
                              void* d_out, int out_size) {
    const float* image = (const float*)d_in[0];
    // d_in[1] = mask (unused by reference forward)
    const float* W_ih  = (const float*)d_in[2];
    const float* W_hh  = (const float*)d_in[3];
    const float* b_ih  = (const float*)d_in[4];
    const float* b_hh  = (const float*)d_in[5];
    // d_in[6] = gp_affected_timesteps; total_t derived from out_size instead
    float* out = (float*)d_out;

    int total_t = out_size / (NPIX * HID);   // = T + (T - gp - 1) = 114

    prep_kernel<<<(128 * G4 + NTHREADS - 1) / NTHREADS, NTHREADS>>>(W_ih, W_hh, b_ih, b_hh);

    cudaFuncSetAttribute(lstm_persist_kernel,
                         cudaFuncAttributeMaxDynamicSharedMemorySize, SMEM_BYTES);
    lstm_persist_kernel<<<NCTA, NTHREADS, SMEM_BYTES>>>(image, out, total_t);
}

// round 4
// speedup vs baseline: 1.0011x; 1.0011x over previous
#include <cuda_runtime.h>

// Problem constants (shapes fixed by the dataset)
#define T_IN     60          // input-driven timesteps
#define CH       128         // input channels
#define NPIX     4096        // batch rows (pixel samples)
#define HID      128         // hidden size
#define G4       512         // 4*HID gate width
#define RBLK     32          // rows per CTA
#define NCTA     (NPIX / RBLK)  // 128 CTAs
#define NTHREADS 256
#define KT       32          // K tile

// Scratch weights (prepared once per launch). ~770 KB device globals (allowed).
__device__ float g_WtCat[256 * G4];  // [k][g]: k<128 -> W_hh[g][k], k>=128 -> W_ih[g][k-128]
__device__ float g_WsumT[128 * G4];  // [k][g]: W_ih[g][k] + W_hh[g][k]  (AR phase)
__device__ float g_bias[G4];         // b_ih + b_hh

__global__ void prep_kernel(const float* __restrict__ W_ih, const float* __restrict__ W_hh,
                            const float* __restrict__ b_ih, const float* __restrict__ b_hh) {
    int idx = blockIdx.x * blockDim.x + threadIdx.x;
    if (idx < 128 * G4) {
        int k = idx >> 9;       // / 512
        int g = idx & 511;
        float wih = W_ih[g * CH + k];
        float whh = W_hh[g * HID + k];
        g_WtCat[k * G4 + g]         = whh;
        g_WtCat[(128 + k) * G4 + g] = wih;
        g_WsumT[k * G4 + g]         = wih + whh;
    }
    if (idx < G4) g_bias[idx] = b_ih[idx] + b_hh[idx];
}

__device__ __forceinline__ float sigm(float x) {
    return __fdividef(1.0f, 1.0f + __expf(-x));
}
__device__ __forceinline__ float tanh_f(float x) {
    // 2*sigmoid(2x)-1 : cancellation-safe for our gate range, MUFU.EX2-based
    return 2.0f * __fdividef(1.0f, 1.0f + __expf(-2.0f * x)) - 1.0f;
}

// Dynamic smem layout (floats):
//   [0,     4096)  sh_h  [32][128]
//   [4096,  8192)  sh_c  [32][128]
//   [8192, 12320)  sh_x  [32][129]  (padded: conflict-free STS of x tile)
//   [12320,28704)  sh_bg [32][512]  (B K-tile, reused as gates buffer)
#define SMEM_FLOATS 28704
#define SMEM_BYTES  (SMEM_FLOATS * 4)

extern __shared__ float smem[];

__global__ __launch_bounds__(NTHREADS, 1)
void lstm_persist_kernel(const float* __restrict__ image, float* __restrict__ out, int total_t) {
    float* sh_h  = smem;
    float* sh_c  = smem + 4096;
    float* sh_x  = smem + 8192;
    float* sh_bg = smem + 12320;

    const int tid = threadIdx.x;
    const int ty  = tid >> 5;   // 0..7  -> row group (4 rows)
    const int tx  = tid & 31;   // 0..31 -> col lane (cols tx + 32*jj)
    const int row_base = blockIdx.x * RBLK;

    // h = c = 0
    for (int i = tid; i < RBLK * HID; i += NTHREADS) { sh_h[i] = 0.0f; sh_c[i] = 0.0f; }

    for (int t = 0; t < total_t; ++t) {
        const bool ph1 = (t < T_IN);
        const float* __restrict__ Bmat = ph1 ? g_WtCat : g_WsumT;
        const int Ktot = ph1 ? 256 : 128;

        if (ph1) {
            // stage x_t tile: sh_x[r][c] = image[t][c][row_base + r]   (coalesced over r)
            for (int i = tid; i < RBLK * CH; i += NTHREADS) {
                int cc = i >> 5;
                int rr = i & 31;
                sh_x[rr * (CH + 1) + cc] =
                    image[((size_t)t * CH + cc) * (size_t)NPIX + row_base + rr];
            }
        }

        // accumulators init with fused bias
        float acc[4][16];
        #pragma unroll
        for (int jj = 0; jj < 16; ++jj) {
            float bv = g_bias[tx + 32 * jj];
            #pragma unroll
            for (int i = 0; i < 4; ++i) acc[i][jj] = bv;
        }

        for (int kt = 0; kt < Ktot; kt += KT) {
            __syncthreads();  // prev tile (or prev-step gates / h) fully consumed
            // stage B K-tile [KT][512] (L2-resident weights)
            {
                const float4* src = (const float4*)(Bmat + (size_t)kt * G4);
                float4* dst = (float4*)sh_bg;
                for (int i = tid; i < KT * G4 / 4; i += NTHREADS) dst[i] = src[i];
            }
            __syncthreads();

            const float* Abase;
            int Astride;
            if (kt < 128) { Abase = sh_h + (ty * 4) * HID + kt;          Astride = HID; }
            else          { Abase = sh_x + (ty * 4) * (CH + 1) + (kt - 128); Astride = CH + 1; }

            #pragma unroll
            for (int kk = 0; kk < KT; ++kk) {
                float a0 = Abase[0 * Astride + kk];   // warp-broadcast LDS
                float a1 = Abase[1 * Astride + kk];
                float a2 = Abase[2 * Astride + kk];
                float a3 = Abase[3 * Astride + kk];
                const float* brow = sh_bg + kk * G4 + tx;  // bank tx: conflict-free
                #pragma unroll
                for (int jj = 0; jj < 16; ++jj) {
                    float bv = brow[32 * jj];
                    acc[0][jj] += a0 * bv;
                    acc[1][jj] += a1 * bv;
                    acc[2][jj] += a2 * bv;
                    acc[3][jj] += a3 * bv;
                }
            }
        }

        __syncthreads();  // all B reads done -> reuse sh_bg for gates
        #pragma unroll
        for (int i = 0; i < 4; ++i) {
            int r = ty * 4 + i;
            #pragma unroll
            for (int jj = 0; jj < 16; ++jj)
                sh_bg[r * G4 + tx + 32 * jj] = acc[i][jj];
        }
        __syncthreads();

        // epilogue: activations + state update + output write
        #pragma unroll
        for (int i = 0; i < 4; ++i) {
            int r = ty * 4 + i;
            #pragma unroll
            for (int jj = 0; jj < 4; ++jj) {
                int j = tx + 32 * jj;
                float gi = sigm  (sh_bg[r * G4 +           j]);
                float gf = sigm  (sh_bg[r * G4 +     HID + j]);
                float gg = tanh_f(sh_bg[r * G4 + 2 * HID + j]);
                float go = sigm  (sh_bg[r * G4 + 3 * HID + j]);
                float cn = gf * sh_c[r * HID + j] + gi * gg;
                sh_c[r * HID + j] = cn;
                float hn = go * tanh_f(cn);
                sh_h[r * HID + j] = hn;
                out[((size_t)(row_base + r) * total_t + t) * HID + j] = hn;
            }
        }
        // next iteration's first __syncthreads orders sh_h/sh_bg reuse
    }
}

extern "C" void kernel_launch(void* const* d_in, const int* in_sizes, int n_in,
                              void* d_out, int out_size) {
    const float* image = (const float*)d_in[0];
    // d_in[1] = mask (unused by reference forward)
    const float* W_ih  = (const float*)d_in[2];
    const float* W_hh  = (const float*)d_in[3];
    const float* b_ih  = (const float*)d_in[4];
    const float* b_hh  = (const float*)d_in[5];
    // d_in[6] = gp_affected_timesteps; total_t derived from out_size instead
    float* out = (float*)d_out;

    int total_t = out_size / (NPIX * HID);   // = T + (T - gp - 1) = 114

    prep_kernel<<<(128 * G4 + NTHREADS - 1) / NTHREADS, NTHREADS>>>(W_ih, W_hh, b_ih, b_hh);

    cudaFuncSetAttribute(lstm_persist_kernel,
                         cudaFuncAttributeMaxDynamicSharedMemorySize, SMEM_BYTES);
    lstm_persist_kernel<<<NCTA, NTHREADS, SMEM_BYTES>>>(image, out, total_t);
}

// round 5
// speedup vs baseline: 1.0898x; 1.0886x over previous
#include <cuda_runtime.h>

// Problem constants (fixed by dataset)
#define T_IN     60
#define CH       128
#define NPIX     4096
#define HID      128
#define G4       512          // 4*HID
#define RBLK     32           // rows per CTA
#define NCTA     (NPIX / RBLK)
#define NTHREADS 256
#define KT       32           // K tile

typedef unsigned long long ull;

// Prepared weights (device globals; ~770KB, allowed)
__device__ __align__(16) float g_WtCat[256 * G4];  // [k][g]: k<128 -> W_hh, k>=128 -> W_ih
__device__ __align__(16) float g_WsumT[128 * G4];  // [k][g]: W_ih + W_hh   (AR phase)
__device__ __align__(16) float g_bias[G4];

__global__ void prep_kernel(const float* __restrict__ W_ih, const float* __restrict__ W_hh,
                            const float* __restrict__ b_ih, const float* __restrict__ b_hh) {
    int idx = blockIdx.x * blockDim.x + threadIdx.x;
    if (idx < 128 * G4) {
        int k = idx >> 9;
        int g = idx & 511;
        float wih = W_ih[g * CH + k];
        float whh = W_hh[g * HID + k];
        g_WtCat[k * G4 + g]         = whh;
        g_WtCat[(128 + k) * G4 + g] = wih;
        g_WsumT[k * G4 + g]         = wih + whh;
    }
    if (idx < G4) g_bias[idx] = b_ih[idx] + b_hh[idx];
}

__device__ __forceinline__ float sigm(float x) {
    return __fdividef(1.0f, 1.0f + __expf(-x));
}
__device__ __forceinline__ float tanh_f(float x) {
    return 2.0f * __fdividef(1.0f, 1.0f + __expf(-2.0f * x)) - 1.0f;
}

// ---- packed f32x2 helpers ----
__device__ __forceinline__ ull dup2(float v) {
    ull r; asm("mov.b64 %0, {%1, %1};" : "=l"(r) : "f"(v)); return r;
}
#define FFMA2(acc, a, b) asm("fma.rn.f32x2 %0, %1, %2, %0;" : "+l"(acc) : "l"(a), "l"(b))

// ---- cp.async helpers ----
#define CP_ASYNC16(dst_u32, src_ptr) \
    asm volatile("cp.async.cg.shared.global [%0], [%1], 16;" :: "r"(dst_u32), "l"(src_ptr))
#define CP_COMMIT()   asm volatile("cp.async.commit_group;")
#define CP_WAIT_ALL() asm volatile("cp.async.wait_all;")

// Dynamic smem layout (floats):
//  [0,     4096)  sh_h [32][128]
//  [4096,  8192)  sh_c [32][128]
//  [8192, 12288)  sh_x [128][32]   (transposed: channel-major, cp.async friendly)
//  [12288,28672)  buf0 [32][512]   (B K-tile, double-buffered; buf of last tile reused for gates)
//  [28672,45056)  buf1 [32][512]
//  [45056,45568)  sh_b [512]
#define SMEM_FLOATS 45568
#define SMEM_BYTES  (SMEM_FLOATS * 4)

extern __shared__ float smem[];

__device__ __forceinline__ void prefetchB(const float* __restrict__ src, float* dst, int tid) {
    unsigned dsh = (unsigned)__cvta_generic_to_shared(dst);
    #pragma unroll
    for (int i = 0; i < 16; ++i) {
        int off = (tid + 256 * i) * 4;        // floats
        CP_ASYNC16(dsh + off * 4, src + off);
    }
}

__device__ __forceinline__ void prefetchX(const float* __restrict__ image, float* sh_x,
                                          int t, int row_base, int tid) {
    unsigned dsh = (unsigned)__cvta_generic_to_shared(sh_x);
    #pragma unroll
    for (int q = 0; q < 4; ++q) {
        int idx  = tid + 256 * q;             // 0..1023
        int c    = idx >> 3;
        int part = idx & 7;                   // 16B chunk within 128B row
        const float* src = image + ((size_t)t * CH + c) * (size_t)NPIX + row_base + part * 4;
        CP_ASYNC16(dsh + (c * RBLK + part * 4) * 4, src);
    }
}

__global__ __launch_bounds__(NTHREADS, 1)
void lstm_persist_kernel(const float* __restrict__ image, float* __restrict__ out, int total_t) {
    float* sh_h = smem;
    float* sh_c = smem + 4096;
    float* sh_x = smem + 8192;
    float* bufs[2] = { smem + 12288, smem + 28672 };
    float* sh_b = smem + 45056;

    const int tid = threadIdx.x;
    const int ty  = tid >> 5;   // 0..7 -> row group (4 rows)
    const int tx  = tid & 31;
    const int row_base = blockIdx.x * RBLK;

    for (int i = tid; i < RBLK * HID; i += NTHREADS) { sh_h[i] = 0.0f; sh_c[i] = 0.0f; }
    for (int i = tid; i < G4; i += NTHREADS) sh_b[i] = g_bias[i];

    // prologue: prefetch first B tile
    prefetchB(g_WtCat, bufs[0], tid);
    CP_COMMIT();

    int par = 0;  // buffer parity of the tile we are about to compute

    for (int t = 0; t < total_t; ++t) {
        const bool ph1 = (t < T_IN);
        const int  nt  = ph1 ? 8 : 4;

        if (ph1) { prefetchX(image, sh_x, t, row_base, tid); CP_COMMIT(); }

        // accumulators: 4 rows x 8 column-pairs (cols 2*tx + 64*m {,+1}), bias-fused
        ull acc0[8], acc1[8], acc2[8], acc3[8];
        {
            const ull* b2 = (const ull*)sh_b;
            #pragma unroll
            for (int m = 0; m < 8; ++m) {
                ull bp = b2[tx + 32 * m];
                acc0[m] = bp; acc1[m] = bp; acc2[m] = bp; acc3[m] = bp;
            }
        }

        for (int i = 0; i < nt; ++i) {
            const int kt = i * KT;
            CP_WAIT_ALL();            // tile (and x) arrived: issued one full tile ago
            __syncthreads();
            const float* bcur = bufs[par];

            if (kt < 128) {
                // A from hidden state: sh_h[r][k]
                const float* hb = sh_h + (ty * 4) * HID + kt;
                #pragma unroll 8
                for (int kk = 0; kk < KT; ++kk) {
                    ull A0 = dup2(hb[0 * HID + kk]);
                    ull A1 = dup2(hb[1 * HID + kk]);
                    ull A2 = dup2(hb[2 * HID + kk]);
                    ull A3 = dup2(hb[3 * HID + kk]);
                    const ull* brow = (const ull*)(bcur + kk * G4);
                    #pragma unroll
                    for (int m = 0; m < 8; ++m) {
                        ull bb = brow[tx + 32 * m];
                        FFMA2(acc0[m], A0, bb);
                        FFMA2(acc1[m], A1, bb);
                        FFMA2(acc2[m], A2, bb);
                        FFMA2(acc3[m], A3, bb);
                    }
                }
            } else {
                // A from input tile: sh_x[c][r] (transposed) -> one broadcast LDS.128
                const float* xb = sh_x + (kt - 128) * RBLK + 4 * ty;
                #pragma unroll 8
                for (int kk = 0; kk < KT; ++kk) {
                    float4 v = *(const float4*)(xb + kk * RBLK);
                    ull A0 = dup2(v.x), A1 = dup2(v.y), A2 = dup2(v.z), A3 = dup2(v.w);
                    const ull* brow = (const ull*)(bcur + kk * G4);
                    #pragma unroll
                    for (int m = 0; m < 8; ++m) {
                        ull bb = brow[tx + 32 * m];
                        FFMA2(acc0[m], A0, bb);
                        FFMA2(acc1[m], A1, bb);
                        FFMA2(acc2[m], A2, bb);
                        FFMA2(acc3[m], A3, bb);
                    }
                }
            }

            __syncthreads();          // compute done -> safe to overwrite other buffer

            // prefetch next tile (overlaps with next iteration / epilogue)
            const bool last_all = (t == total_t - 1) && (i == nt - 1);
            if (!last_all) {
                const float* nB; int nkt;
                if (i + 1 < nt) { nB = ph1 ? g_WtCat : g_WsumT; nkt = (i + 1) * KT; }
                else            { nB = (t + 1 < T_IN) ? g_WtCat : g_WsumT; nkt = 0; }
                prefetchB(nB + (size_t)nkt * G4, bufs[par ^ 1], tid);
                CP_COMMIT();
            }
            par ^= 1;
        }

        // gates reshuffle through the buffer of the LAST tile (par^1); the
        // in-flight prefetch targets bufs[par] -> no conflict.
        float* gates = bufs[par ^ 1];
        #pragma unroll
        for (int i = 0; i < 4; ++i) {
            ull* gr = (ull*)(gates + (ty * 4 + i) * G4);
            #pragma unroll
            for (int m = 0; m < 8; ++m) {
                ull v = (i == 0) ? acc0[m] : (i == 1) ? acc1[m] : (i == 2) ? acc2[m] : acc3[m];
                gr[tx + 32 * m] = v;
            }
        }
        __syncthreads();

        // epilogue: activations + state update + output
        #pragma unroll
        for (int i = 0; i < 4; ++i) {
            int r = ty * 4 + i;
            #pragma unroll
            for (int jj = 0; jj < 4; ++jj) {
                int j = tx + 32 * jj;
                float gi = sigm  (gates[r * G4 +           j]);
                float gf = sigm  (gates[r * G4 +     HID + j]);
                float gg = tanh_f(gates[r * G4 + 2 * HID + j]);
                float go = sigm  (gates[r * G4 + 3 * HID + j]);
                float cn = gf * sh_c[r * HID + j] + gi * gg;
                sh_c[r * HID + j] = cn;
                float hn = go * tanh_f(cn);
                sh_h[r * HID + j] = hn;
                out[((size_t)(row_base + r) * total_t + t) * HID + j] = hn;
            }
        }
        // next iteration's first __syncthreads (after wait_all) orders sh_h reuse
    }
}

extern "C" void kernel_launch(void* const* d_in, const int* in_sizes, int n_in,
                              void* d_out, int out_size) {
    const float* image = (const float*)d_in[0];
    const float* W_ih  = (const float*)d_in[2];
    const float* W_hh  = (const float*)d_in[3];
    const float* b_ih  = (const float*)d_in[4];
    const float* b_hh  = (const float*)d_in[5];
    float* out = (float*)d_out;

    int total_t = out_size / (NPIX * HID);   // 114

    prep_kernel<<<(128 * G4 + NTHREADS - 1) / NTHREADS, NTHREADS>>>(W_ih, W_hh, b_ih, b_hh);

    cudaFuncSetAttribute(lstm_persist_kernel,
                         cudaFuncAttributeMaxDynamicSharedMemorySize, SMEM_BYTES);
    lstm_persist_kernel<<<NCTA, NTHREADS, SMEM_BYTES>>>(image, out, total_t);
}

// round 7
// speedup vs baseline: 1.3873x; 1.2730x over previous
#include <cuda_runtime.h>

// Problem constants (fixed by dataset)
#define T_IN  60
#define CH    128
#define NPIX  4096
#define HID   128
#define G4    512            // 4*HID
#define RBLK  32             // rows per CTA
#define NCTA  (NPIX / RBLK)  // 128
#define NTH   512            // threads per CTA (16 warps)
#define KT    32             // K tile
#define PH    34             // hT pitch (stride 17 in 8B banks: conflict-free STS.64)

typedef unsigned long long ull;

// Prepared weights (device globals, ~770KB; allowed)
__device__ __align__(16) float g_WtCat[256 * G4];  // [k][g]: k<128 -> W_hh, k>=128 -> W_ih
__device__ __align__(16) float g_WsumT[128 * G4];  // [k][g]: W_ih + W_hh (AR phase)
__device__ __align__(16) float g_bias[G4];

__global__ void prep_kernel(const float* __restrict__ W_ih, const float* __restrict__ W_hh,
                            const float* __restrict__ b_ih, const float* __restrict__ b_hh) {
    int idx = blockIdx.x * blockDim.x + threadIdx.x;
    if (idx < 128 * G4) {
        int k = idx >> 9;
        int g = idx & 511;
        float wih = W_ih[g * CH + k];
        float whh = W_hh[g * HID + k];
        g_WtCat[k * G4 + g]         = whh;
        g_WtCat[(128 + k) * G4 + g] = wih;
        g_WsumT[k * G4 + g]         = wih + whh;
    }
    if (idx < G4) g_bias[idx] = b_ih[idx] + b_hh[idx];
}

__device__ __forceinline__ float sigm(float x) {
    return __fdividef(1.0f, 1.0f + __expf(-x));
}
__device__ __forceinline__ float tanh_f(float x) {
    return 2.0f * __fdividef(1.0f, 1.0f + __expf(-2.0f * x)) - 1.0f;
}

// packed f32x2 helpers
__device__ __forceinline__ ull dup2(float v) {
    ull r; asm("mov.b64 %0, {%1, %1};" : "=l"(r) : "f"(v)); return r;
}
#define FFMA2(acc, a, b) asm("fma.rn.f32x2 %0, %1, %2, %0;" : "+l"(acc) : "l"(a), "l"(b))
#define UNPACK2(lo, hi, v) asm("mov.b64 {%0, %1}, %2;" : "=f"(lo), "=f"(hi) : "l"(v))

// cp.async helpers
#define CP_ASYNC16(dst_u32, src_ptr) \
    asm volatile("cp.async.cg.shared.global [%0], [%1], 16;" :: "r"(dst_u32), "l"(src_ptr))
#define CP_COMMIT()   asm volatile("cp.async.commit_group;")
#define CP_WAIT_ALL() asm volatile("cp.async.wait_all;")

// Dynamic smem layout (floats):
//   [0,     4352)  hT   [128][34]  h transposed: hT[k][r] (pairs over rows)
//   [4352,  8448)  sh_c [32][128]
//   [8448, 12544)  sh_x [128][32]  x transposed (cp.async-friendly, row pairs)
//   [12544,28928)  buf0 [32][512]  (weight K-tile, double buffered)
//   [28928,45312)  buf1 [32][512]
//   [45312,45824)  sh_b [512]
#define OFF_C  4352
#define OFF_X  8448
#define OFF_B0 12544
#define OFF_B1 28928
#define OFF_BI 45312
#define SMEM_FLOATS 45824
#define SMEM_BYTES  (SMEM_FLOATS * 4)

extern __shared__ float smem[];

__device__ __forceinline__ void prefetchB(const float* __restrict__ src, float* dst, int tid) {
    unsigned dsh = (unsigned)__cvta_generic_to_shared(dst);
    #pragma unroll
    for (int i = 0; i < 8; ++i) {
        int off = (tid + NTH * i) * 4;        // floats (16B chunks)
        CP_ASYNC16(dsh + off * 4, src + off);
    }
}

__device__ __forceinline__ void prefetchX(const float* __restrict__ image, float* sh_x,
                                          int t, int row_base, int tid) {
    unsigned dsh = (unsigned)__cvta_generic_to_shared(sh_x);
    #pragma unroll
    for (int q = 0; q < 2; ++q) {
        int idx  = tid + NTH * q;             // 0..1023
        int c    = idx >> 3;                  // channel
        int part = idx & 7;                   // 16B chunk within 128B of rows
        const float* src = image + ((size_t)t * CH + c) * (size_t)NPIX + row_base + part * 4;
        CP_ASYNC16(dsh + (c * RBLK + part * 4) * 4, src);
    }
}

__global__ __launch_bounds__(NTH, 1)
void lstm_persist_kernel(const float* __restrict__ image, float* __restrict__ out, int total_t) {
    float* hT   = smem;
    float* shc  = smem + OFF_C;
    float* shx  = smem + OFF_X;
    float* bufs[2] = { smem + OFF_B0, smem + OFF_B1 };
    float* shb  = smem + OFF_BI;

    const int tid = threadIdx.x;
    const int tx  = tid & 31;
    const int w   = tid >> 5;     // warp 0..15
    const int rg  = w >> 2;       // row group: rows rg*8 .. rg*8+7
    const int cq  = w & 3;        // column quarter
    const int jc  = tx + 32 * cq; // this thread's column within each gate block (0..127)
    const int row_base = blockIdx.x * RBLK;

    for (int i = tid; i < 128 * PH; i += NTH) hT[i] = 0.0f;
    for (int i = tid; i < RBLK * HID; i += NTH) shc[i] = 0.0f;
    for (int i = tid; i < G4; i += NTH) shb[i] = g_bias[i];

    // prologue: prefetch first weight tile + x(t=0) (one group)
    prefetchB(g_WtCat, bufs[0], tid);
    prefetchX(image, shx, 0, row_base, tid);
    CP_COMMIT();
    __syncthreads();   // orders shb/hT/shc init for all warps

    int par = 0;

    for (int t = 0; t < total_t; ++t) {
        const bool ph1 = (t < T_IN);
        const int  nt  = ph1 ? 8 : 4;

        // accumulators: 4 row-pairs x 4 gate blocks, bias-fused.
        // acc[q][g] holds gates for rows (rg*8+2q, rg*8+2q+1), col jc + 128*g
        ull acc[4][4];
        #pragma unroll
        for (int g = 0; g < 4; ++g) {
            ull bb = dup2(shb[jc + 128 * g]);
            #pragma unroll
            for (int q = 0; q < 4; ++q) acc[q][g] = bb;
        }

        for (int i = 0; i < nt; ++i) {
            CP_WAIT_ALL();           // tile i arrived (issued a full tile of compute ago)
            __syncthreads();         // all warps done with bufs[par^1]; data visible

            // issue NEXT prefetch before computing: true overlap.
            const bool last_all = (t == total_t - 1) && (i == nt - 1);
            if (!last_all) {
                const float* nB; int nkt;
                if (i + 1 < nt) { nB = ph1 ? g_WtCat : g_WsumT; nkt = (i + 1) * KT; }
                else            { nB = (t + 1 < T_IN) ? g_WtCat : g_WsumT; nkt = 0; }
                prefetchB(nB + (size_t)nkt * G4, bufs[par ^ 1], tid);
                // x(t) staged at tile 0 of step t itself: the tile-0 barrier
                // guarantees every warp finished step t-1's shx reads (race-free);
                // arrival is forced by tile-1's wait, deadline is tile 4.
                if (ph1 && i == 0 && t > 0)
                    prefetchX(image, shx, t, row_base, tid);
                CP_COMMIT();
            }

            const float* bc = bufs[par];
            const int kt = i * KT;

            if (kt < 128) {
                // A from transposed hidden state hT[k][r] (row-pair LDS.64 broadcast)
                const float* ab = hT + kt * PH + rg * 8;
                #pragma unroll 4
                for (int kk = 0; kk < KT; ++kk) {
                    const float* br = bc + kk * G4 + jc;
                    ull a0 = *(const ull*)(ab + kk * PH + 0);
                    ull a1 = *(const ull*)(ab + kk * PH + 2);
                    ull a2 = *(const ull*)(ab + kk * PH + 4);
                    ull a3 = *(const ull*)(ab + kk * PH + 6);
                    ull b0 = dup2(br[0]);
                    ull b1 = dup2(br[128]);
                    ull b2 = dup2(br[256]);
                    ull b3 = dup2(br[384]);
                    FFMA2(acc[0][0], a0, b0); FFMA2(acc[0][1], a0, b1);
                    FFMA2(acc[0][2], a0, b2); FFMA2(acc[0][3], a0, b3);
                    FFMA2(acc[1][0], a1, b0); FFMA2(acc[1][1], a1, b1);
                    FFMA2(acc[1][2], a1, b2); FFMA2(acc[1][3], a1, b3);
                    FFMA2(acc[2][0], a2, b0); FFMA2(acc[2][1], a2, b1);
                    FFMA2(acc[2][2], a2, b2); FFMA2(acc[2][3], a2, b3);
                    FFMA2(acc[3][0], a3, b0); FFMA2(acc[3][1], a3, b1);
                    FFMA2(acc[3][2], a3, b2); FFMA2(acc[3][3], a3, b3);
                }
            } else {
                // A from transposed input tile shx[c][r]
                const float* ab = shx + (kt - 128) * RBLK + rg * 8;
                #pragma unroll 4
                for (int kk = 0; kk < KT; ++kk) {
                    const float* br = bc + kk * G4 + jc;
                    ull a0 = *(const ull*)(ab + kk * RBLK + 0);
                    ull a1 = *(const ull*)(ab + kk * RBLK + 2);
                    ull a2 = *(const ull*)(ab + kk * RBLK + 4);
                    ull a3 = *(const ull*)(ab + kk * RBLK + 6);
                    ull b0 = dup2(br[0]);
                    ull b1 = dup2(br[128]);
                    ull b2 = dup2(br[256]);
                    ull b3 = dup2(br[384]);
                    FFMA2(acc[0][0], a0, b0); FFMA2(acc[0][1], a0, b1);
                    FFMA2(acc[0][2], a0, b2); FFMA2(acc[0][3], a0, b3);
                    FFMA2(acc[1][0], a1, b0); FFMA2(acc[1][1], a1, b1);
                    FFMA2(acc[1][2], a1, b2); FFMA2(acc[1][3], a1, b3);
                    FFMA2(acc[2][0], a2, b0); FFMA2(acc[2][1], a2, b1);
                    FFMA2(acc[2][2], a2, b2); FFMA2(acc[2][3], a2, b3);
                    FFMA2(acc[3][0], a3, b0); FFMA2(acc[3][1], a3, b1);
                    FFMA2(acc[3][2], a3, b2); FFMA2(acc[3][3], a3, b3);
                }
            }
            par ^= 1;
        }

        // phase2: all tiles read hT -> must drain before epilogue overwrites it.
        // phase1: tiles 4..7 read shx/bufs only; hT reads (tiles 0..3) are fenced
        // by the tile-4..7 top barriers, so the epilogue may proceed unsynced.
        if (!ph1) __syncthreads();

        // epilogue: this thread owns ALL FOUR gates for its 8 (row, jc) cells.
        // Entire LSTM cell update in registers; only sh_c / hT / out touched.
        #pragma unroll
        for (int q = 0; q < 4; ++q) {
            float i0, i1, f0, f1, g0, g1, o0, o1;
            UNPACK2(i0, i1, acc[q][0]);
            UNPACK2(f0, f1, acc[q][1]);
            UNPACK2(g0, g1, acc[q][2]);
            UNPACK2(o0, o1, acc[q][3]);
            int r0 = rg * 8 + 2 * q;
            float c0 = shc[r0 * HID + jc];
            float c1 = shc[(r0 + 1) * HID + jc];
            float cn0 = sigm(f0) * c0 + sigm(i0) * tanh_f(g0);
            float cn1 = sigm(f1) * c1 + sigm(i1) * tanh_f(g1);
            shc[r0 * HID + jc]       = cn0;
            shc[(r0 + 1) * HID + jc] = cn1;
            float hn0 = sigm(o0) * tanh_f(cn0);
            float hn1 = sigm(o1) * tanh_f(cn1);
            *(float2*)(hT + jc * PH + r0) = make_float2(hn0, hn1);
            out[((size_t)(row_base + r0)     * total_t + t) * HID + jc] = hn0;
            out[((size_t)(row_base + r0 + 1) * total_t + t) * HID + jc] = hn1;
        }
        // next step's tile-0 top __syncthreads orders hT writes vs GEMM reads
    }
}

extern "C" void kernel_launch(void* const* d_in, const int* in_sizes, int n_in,
                              void* d_out, int out_size) {
    const float* image = (const float*)d_in[0];
    // d_in[1] = mask (unused by reference forward)
    const float* W_ih  = (const float*)d_in[2];
    const float* W_hh  = (const float*)d_in[3];
    const float* b_ih  = (const float*)d_in[4];
    const float* b_hh  = (const float*)d_in[5];
    float* out = (float*)d_out;

    int total_t = out_size / (NPIX * HID);   // 114

    prep_kernel<<<(128 * G4 + 255) / 256, 256>>>(W_ih, W_hh, b_ih, b_hh);

    cudaFuncSetAttribute(lstm_persist_kernel,
                         cudaFuncAttributeMaxDynamicSharedMemorySize, SMEM_BYTES);
    lstm_persist_kernel<<<NCTA, NTH, SMEM_BYTES>>>(image, out, total_t);
}